// round 7
// baseline (speedup 1.0000x reference)
#include <cuda_runtime.h>
#include <cstdint>

// PyramidROIAlign, warp-persistent: each warp processes 5 consecutive pool
// points (98000 = 2450 blocks x 8 warps x 5 points, exact).
//   boxes: (2, 1000, 4) f32; p2: (2, 256, 256, 256) f32 NHWC
//   out:   (2, 1000, 7, 7, 256) f32
//
// KEY FACT (proved R6): for any normalized box h,w <= 1,
// clip(round(log2(sqrt(hw)/0.21875)),2,5) == 2 always -> only p2 sampled.
//
// Per warp-iteration: incremental (roi,py,px) tracking (no divisions),
// box reloaded only on ROI wrap; 8 batched independent LDG.128
// (4 corners x 2 channel halves), 2 lerps, 2 streaming STG.128.

#define BATCH   2
#define NROI    1000
#define POOLH   7
#define POOLW   7
#define NCH     256
#define NCH4    (NCH / 4)            // 64
#define POINTS  (POOLH * POOLW)      // 49
#define NPTS    (BATCH * NROI * POINTS)   // 98000
#define FH      256                  // p2 spatial size
#define PPW     5                    // points per warp
#define NWARPS  (NPTS / PPW)         // 19600
#define NBLK    (NWARPS / 8)         // 2450

__device__ __forceinline__ float4 lerp2(const float4 v00, const float4 v01,
                                        const float4 v10, const float4 v11,
                                        const float wx, const float wy)
{
    float4 r;
    float t, bo;
    t  = v00.x + wx * (v01.x - v00.x);
    bo = v10.x + wx * (v11.x - v10.x);
    r.x = t + wy * (bo - t);
    t  = v00.y + wx * (v01.y - v00.y);
    bo = v10.y + wx * (v11.y - v10.y);
    r.y = t + wy * (bo - t);
    t  = v00.z + wx * (v01.z - v00.z);
    bo = v10.z + wx * (v11.z - v10.z);
    r.z = t + wy * (bo - t);
    t  = v00.w + wx * (v01.w - v00.w);
    bo = v10.w + wx * (v11.w - v10.w);
    r.w = t + wy * (bo - t);
    return r;
}

__global__ __launch_bounds__(256, 6) void pyramid_roi_align_kernel(
    const float* __restrict__ boxes,
    const float* __restrict__ p2,
    float4* __restrict__ out)
{
    const int lane = threadIdx.x & 31;
    const int wrp  = threadIdx.x >> 5;
    const int W    = blockIdx.x * 8 + wrp;   // warp id 0..19599
    const int pt0  = W * PPW;                // first point

    // Decompose once (compiler emits magic-multiply, no real div).
    int roi = pt0 / POINTS;
    int rem = pt0 - roi * POINTS;
    int py  = rem / POOLW;
    int px  = rem - py * POOLW;

    // Load box for current ROI (L1-resident 32KB array).
    float4 bx = __ldg((const float4*)(boxes) + roi);

    const float4* __restrict__ f4 = (const float4*)p2;
    float4* __restrict__ o = out + (long long)pt0 * NCH4 + lane;

    const float Hm1 = (float)(FH - 1);

    #pragma unroll
    for (int i = 0; i < PPW; i++) {
        const int b = roi >= NROI ? 1 : 0;
        const float y1 = bx.x, x1 = bx.y, y2 = bx.z, x2 = bx.w;
        const float h = y2 - y1;
        const float w = x2 - x1;

        const float ty = (float)py * (1.0f / 6.0f);
        const float tx = (float)px * (1.0f / 6.0f);
        const float ysf = (y1 + h * ty) * Hm1;
        const float xsf = (x1 + w * tx) * Hm1;

        const float y0f = floorf(ysf);
        const float x0f = floorf(xsf);
        const float wy = ysf - y0f;   // weights from UNCLAMPED floor (ref)
        const float wx = xsf - x0f;

        const int y0  = min(max((int)y0f, 0), FH - 1);
        const int y1i = min(max((int)y0f + 1, 0), FH - 1);
        const int x0  = min(max((int)x0f, 0), FH - 1);
        const int x1i = min(max((int)x0f + 1, 0), FH - 1);

        // NHWC float4 view: f4[((b*256 + y)*256 + x)*64 + c]
        const int rowb0 = (b * FH + y0)  * FH;
        const int rowb1 = (b * FH + y1i) * FH;
        const float4* __restrict__ q00 = f4 + (rowb0 + x0 ) * NCH4 + lane;
        const float4* __restrict__ q01 = f4 + (rowb0 + x1i) * NCH4 + lane;
        const float4* __restrict__ q10 = f4 + (rowb1 + x0 ) * NCH4 + lane;
        const float4* __restrict__ q11 = f4 + (rowb1 + x1i) * NCH4 + lane;

        // 8 batched independent gathers (channels lane, lane+32).
        const float4 a00 = __ldg(q00);
        const float4 a01 = __ldg(q01);
        const float4 a10 = __ldg(q10);
        const float4 a11 = __ldg(q11);
        const float4 b00 = __ldg(q00 + 32);
        const float4 b01 = __ldg(q01 + 32);
        const float4 b10 = __ldg(q10 + 32);
        const float4 b11 = __ldg(q11 + 32);

        const float4 ra = lerp2(a00, a01, a10, a11, wx, wy);
        const float4 rb = lerp2(b00, b01, b10, b11, wx, wy);

        __stcs(o,      ra);
        __stcs(o + 32, rb);
        o += NCH4;

        // Incremental point advance (no divisions).
        px++;
        if (px == POOLW) {
            px = 0;
            py++;
            if (py == POOLH) {
                py = 0;
                roi++;
                bx = __ldg((const float4*)(boxes) + roi);
            }
        }
    }
}

extern "C" void kernel_launch(void* const* d_in, const int* in_sizes, int n_in,
                              void* d_out, int out_size)
{
    const float* boxes = (const float*)d_in[0];
    const float* p2    = (const float*)d_in[1];
    float4* out = (float4*)d_out;

    pyramid_roi_align_kernel<<<NBLK, 256>>>(boxes, p2, out);
}

// round 8
// speedup vs baseline: 1.2493x; 1.2493x over previous
#include <cuda_runtime.h>
#include <cstdint>

// PyramidROIAlign, warp-per-pool-point, 256-bit memory ops (sm_100a+).
//   boxes: (2, 1000, 4) f32; p2: (2, 256, 256, 256) f32 NHWC
//   out:   (2, 1000, 7, 7, 256) f32
//
// KEY FACT (proved R6): for any normalized box h,w <= 1,
// clip(round(log2(sqrt(hw)/0.21875)),2,5) == 2 always -> only p2 sampled.
//
// 98000 points = 12250 blocks x 8 warps (exact, no tail, no loop — R7 showed
// serial loops kill MLP). Each lane owns 8 consecutive floats; one warp
// covers a full 1KB channel row per LDG.256. Per point: 4 batched
// independent ld.global.nc.v8.f32 + 1 st.global.cs.v8.f32.

#define BATCH   2
#define NROI    1000
#define POOLH   7
#define POOLW   7
#define NCH     256
#define POINTS  (POOLH * POOLW)      // 49
#define NPTS    (BATCH * NROI * POINTS)   // 98000
#define FH      256                  // p2 spatial size

#define LDG256(r, p)                                                        \
    asm volatile("ld.global.nc.v8.f32 {%0,%1,%2,%3,%4,%5,%6,%7}, [%8];"      \
        : "=f"((r)[0]), "=f"((r)[1]), "=f"((r)[2]), "=f"((r)[3]),            \
          "=f"((r)[4]), "=f"((r)[5]), "=f"((r)[6]), "=f"((r)[7])             \
        : "l"(p))

#define STG256CS(p, r)                                                      \
    asm volatile("st.global.cs.v8.f32 [%0], {%1,%2,%3,%4,%5,%6,%7,%8};"      \
        :: "l"(p),                                                           \
           "f"((r)[0]), "f"((r)[1]), "f"((r)[2]), "f"((r)[3]),               \
           "f"((r)[4]), "f"((r)[5]), "f"((r)[6]), "f"((r)[7])                \
        : "memory")

__global__ __launch_bounds__(256, 4) void pyramid_roi_align_kernel(
    const float* __restrict__ boxes,
    const float* __restrict__ p2,
    float* __restrict__ out)
{
    const int lane = threadIdx.x & 31;
    const int wrp  = threadIdx.x >> 5;
    const int pt   = blockIdx.x * 8 + wrp;    // 0..97999, exact

    // ---- warp-uniform param computation (registers only) ----
    const int roi = pt / POINTS;              // IMAD magic div
    const int ppt = pt - roi * POINTS;        // 0..48
    const int py  = ppt / POOLW;
    const int px  = ppt - py * POOLW;
    const int b   = roi >= NROI ? 1 : 0;

    const float4 bx = __ldg((const float4*)(boxes) + roi);
    const float y1 = bx.x, x1 = bx.y, y2 = bx.z, x2 = bx.w;
    const float h = y2 - y1;
    const float w = x2 - x1;

    // level == 2 always (proof in header): sample p2, H = W = 256.
    const float Hm1 = (float)(FH - 1);
    const float ty = (float)py * (1.0f / 6.0f);
    const float tx = (float)px * (1.0f / 6.0f);
    const float ysf = (y1 + h * ty) * Hm1;
    const float xsf = (x1 + w * tx) * Hm1;

    const float y0f = floorf(ysf);
    const float x0f = floorf(xsf);
    const float wy = ysf - y0f;   // weights from UNCLAMPED floor (matches ref)
    const float wx = xsf - x0f;

    const int y0  = min(max((int)y0f, 0), FH - 1);
    const int y1i = min(max((int)y0f + 1, 0), FH - 1);
    const int x0  = min(max((int)x0f, 0), FH - 1);
    const int x1i = min(max((int)x0f + 1, 0), FH - 1);

    // NHWC: p2[((b*256 + y)*256 + x)*256 + c]; lane owns floats [8*lane, 8*lane+8)
    const int rowb0 = (b * FH + y0)  * FH;
    const int rowb1 = (b * FH + y1i) * FH;
    const int co = lane * 8;
    const float* q00 = p2 + (size_t)(rowb0 + x0 ) * NCH + co;
    const float* q01 = p2 + (size_t)(rowb0 + x1i) * NCH + co;
    const float* q10 = p2 + (size_t)(rowb1 + x0 ) * NCH + co;
    const float* q11 = p2 + (size_t)(rowb1 + x1i) * NCH + co;

    // ---- 4 batched independent 256-bit gathers (1KB/row/warp) ----
    float v00[8], v01[8], v10[8], v11[8];
    LDG256(v00, q00);
    LDG256(v01, q01);
    LDG256(v10, q10);
    LDG256(v11, q11);

    float r[8];
    #pragma unroll
    for (int i = 0; i < 8; i++) {
        const float t  = v00[i] + wx * (v01[i] - v00[i]);
        const float bo = v10[i] + wx * (v11[i] - v10[i]);
        r[i] = t + wy * (bo - t);
    }

    float* o = out + (size_t)pt * NCH + co;
    STG256CS(o, r);
}

extern "C" void kernel_launch(void* const* d_in, const int* in_sizes, int n_in,
                              void* d_out, int out_size)
{
    const float* boxes = (const float*)d_in[0];
    const float* p2    = (const float*)d_in[1];
    float* out = (float*)d_out;

    pyramid_roi_align_kernel<<<NPTS / 8, 256>>>(boxes, p2, out);
}

// round 9
// speedup vs baseline: 1.4080x; 1.1271x over previous
#include <cuda_runtime.h>
#include <cstdint>

// PyramidROIAlign, warp-per-pool-point (R6 structure, 128-thread CTAs).
//   boxes: (2, 1000, 4) f32; p2: (2, 256, 256, 256) f32 NHWC
//   out:   (2, 1000, 7, 7, 256) f32
//
// KEY FACT (proved R6): for any normalized box h,w <= 1,
// clip(round(log2(sqrt(hw)/0.21875)),2,5) == 2 always -> only p2 sampled.
//
// Session law (R4/R7/R8): maximize (resident warps) x (batched loads/warp).
// R6 optimum: 32 regs, 8 batched LDG.128 per warp, 64 warps/SM.
// This round: identical per-warp code, CTA size 256 -> 128 to halve block
// retire granularity (cross-CTA L1tex-queue spread holds dead warp slots in
// wide CTAs). 98000 points = 24500 blocks x 4 warps, exact.

#define BATCH   2
#define NROI    1000
#define POOLH   7
#define POOLW   7
#define NCH     256
#define NCH4    (NCH / 4)            // 64
#define POINTS  (POOLH * POOLW)      // 49
#define NPTS    (BATCH * NROI * POINTS)   // 98000
#define FH      256                  // p2 spatial size

__device__ __forceinline__ float4 lerp2(const float4 v00, const float4 v01,
                                        const float4 v10, const float4 v11,
                                        const float wx, const float wy)
{
    float4 r;
    float t, bo;
    t  = v00.x + wx * (v01.x - v00.x);
    bo = v10.x + wx * (v11.x - v10.x);
    r.x = t + wy * (bo - t);
    t  = v00.y + wx * (v01.y - v00.y);
    bo = v10.y + wx * (v11.y - v10.y);
    r.y = t + wy * (bo - t);
    t  = v00.z + wx * (v01.z - v00.z);
    bo = v10.z + wx * (v11.z - v10.z);
    r.z = t + wy * (bo - t);
    t  = v00.w + wx * (v01.w - v00.w);
    bo = v10.w + wx * (v11.w - v10.w);
    r.w = t + wy * (bo - t);
    return r;
}

__global__ __launch_bounds__(128, 16) void pyramid_roi_align_kernel(
    const float* __restrict__ boxes,
    const float* __restrict__ p2,
    float4* __restrict__ out)
{
    const int lane = threadIdx.x & 31;
    const int wrp  = threadIdx.x >> 5;
    const int pt   = blockIdx.x * 4 + wrp;    // 0..97999, exact

    // ---- warp-uniform param computation (registers only) ----
    const int roi = pt / POINTS;              // IMAD magic div
    const int ppt = pt - roi * POINTS;        // 0..48
    const int py  = ppt / POOLW;
    const int px  = ppt - py * POOLW;
    const int b   = roi >= NROI ? 1 : 0;

    const float4 bx = __ldg((const float4*)(boxes) + roi);
    const float y1 = bx.x, x1 = bx.y, y2 = bx.z, x2 = bx.w;
    const float h = y2 - y1;
    const float w = x2 - x1;

    // level == 2 always (proof in header): sample p2, H = W = 256.
    const float Hm1 = (float)(FH - 1);
    const float ty = (float)py * (1.0f / 6.0f);
    const float tx = (float)px * (1.0f / 6.0f);
    const float ysf = (y1 + h * ty) * Hm1;
    const float xsf = (x1 + w * tx) * Hm1;

    const float y0f = floorf(ysf);
    const float x0f = floorf(xsf);
    const float wy = ysf - y0f;   // weights from UNCLAMPED floor (matches ref)
    const float wx = xsf - x0f;

    const int y0  = min(max((int)y0f, 0), FH - 1);
    const int y1i = min(max((int)y0f + 1, 0), FH - 1);
    const int x0  = min(max((int)x0f, 0), FH - 1);
    const int x1i = min(max((int)x0f + 1, 0), FH - 1);

    // NHWC float4 view: p2_4[((b*256 + y)*256 + x)*64 + c]
    const float4* __restrict__ f4 = (const float4*)p2;
    const int rowb0 = (b * FH + y0)  * FH;
    const int rowb1 = (b * FH + y1i) * FH;
    const float4* __restrict__ q00 = f4 + (rowb0 + x0 ) * NCH4 + lane;
    const float4* __restrict__ q01 = f4 + (rowb0 + x1i) * NCH4 + lane;
    const float4* __restrict__ q10 = f4 + (rowb1 + x0 ) * NCH4 + lane;
    const float4* __restrict__ q11 = f4 + (rowb1 + x1i) * NCH4 + lane;

    // ---- 8 batched independent gathers (channels lane, lane+32) ----
    const float4 a00 = __ldg(q00);
    const float4 a01 = __ldg(q01);
    const float4 a10 = __ldg(q10);
    const float4 a11 = __ldg(q11);
    const float4 b00 = __ldg(q00 + 32);
    const float4 b01 = __ldg(q01 + 32);
    const float4 b10 = __ldg(q10 + 32);
    const float4 b11 = __ldg(q11 + 32);

    const float4 ra = lerp2(a00, a01, a10, a11, wx, wy);
    const float4 rb = lerp2(b00, b01, b10, b11, wx, wy);

    // out point block: pt * 64 float4
    float4* __restrict__ o = out + (long long)pt * NCH4 + lane;
    __stcs(o,      ra);
    __stcs(o + 32, rb);
}

extern "C" void kernel_launch(void* const* d_in, const int* in_sizes, int n_in,
                              void* d_out, int out_size)
{
    const float* boxes = (const float*)d_in[0];
    const float* p2    = (const float*)d_in[1];
    float4* out = (float4*)d_out;

    pyramid_roi_align_kernel<<<NPTS / 4, 128>>>(boxes, p2, out);
}